// round 5
// baseline (speedup 1.0000x reference)
#include <cuda_runtime.h>
#include <math.h>

// ---------------- problem constants ----------------
#define B_   64
#define C_   256
#define HW_  4096            // 64*64
#define TILE 16              // spatial positions per tile
#define SUBT 16              // tiles per CTA
#define NBLK 16              // CTAs per batch  (16*16*16 = 4096)
#define PLANES 128
#define HIDDEN 16
#define K_   8
#define ATT_CH 4
#define EPS_ 1e-5f

// ---------------- device scratch (zero-init at load; last CTA re-zeros) ----------------
__device__ float    g_sumc[B_ * C_];
__device__ float    g_num [B_ * C_];
__device__ float    g_D   [B_];
__device__ float    g_summ[B_];
__device__ unsigned g_cnt [B_];

// ---------------- dynamic smem layout (floats) ----------------
#define SX0  0                 // 4096 f (16 KB) tile buffer 0, row stride 16
#define SX1  4096              // 4096 f         tile buffer 1
#define AL   8192              // 128 f  logit partials [8 warp][16 pos]
#define AM   8320              // 128 f  max partials
#define SE   8448              // 16 f   exp weights
#define SMEM_FLOATS 8480
#define SMEM_BYTES  (SMEM_FLOATS * 4)   // 33920 B -> 6 CTAs/SM

// ---------------- cp.async helpers ----------------
__device__ __forceinline__ void cp16(float* s, const float4* g) {
    unsigned sa = (unsigned)__cvta_generic_to_shared(s);
    asm volatile("cp.async.cg.shared.global [%0], [%1], 16;\n" :: "r"(sa), "l"(g));
}
#define CP_COMMIT()  asm volatile("cp.async.commit_group;\n")
#define CP_WAIT(n)   asm volatile("cp.async.wait_group %0;\n" :: "n"(n))

__global__ __launch_bounds__(256, 6) void fused(
        const float* __restrict__ x,
        const float* __restrict__ w_mask, const float* __restrict__ b_mask,
        const float* __restrict__ w_cm1, const float* __restrict__ b_cm1,
        const float* __restrict__ ln_w,  const float* __restrict__ ln_b,
        const float* __restrict__ w_cm2, const float* __restrict__ b_cm2,
        const float* __restrict__ w_net1, const float* __restrict__ w_net2,
        const float* __restrict__ w_fc,
        const float* __restrict__ bn_w,  const float* __restrict__ bn_b,
        const float* __restrict__ bn_mean, const float* __restrict__ bn_var,
        const float* __restrict__ w_kfc,
        float* __restrict__ out) {
    extern __shared__ __align__(16) float sm[];
    __shared__ int s_last;

    const int t    = threadIdx.x;    // 0..255
    const int lane = t & 31;
    const int wp   = t >> 5;
    const int b    = blockIdx.x >> 4;         // batch
    const int blk  = blockIdx.x & (NBLK - 1); // block within batch
    const int tile0 = blk * SUBT;

    const int cg = t >> 2;           // channel group 0..63 (4 channels each)
    const int q  = t & 3;            // position quad 0..3

    // hoisted mask weights for this thread's 4 channels
    const float4 wv = *reinterpret_cast<const float4*>(w_mask + cg * 4);
    const float wreg[4] = {wv.x, wv.y, wv.z, wv.w};
    const float bm = b_mask[0];

    const float4* xb = reinterpret_cast<const float4*>(x) + (size_t)b * C_ * (HW_ / 4);

    // per-thread accumulators across tiles (channel = t)
    float4 sv  = make_float4(0.f, 0.f, 0.f, 0.f);
    float4 sve = make_float4(0.f, 0.f, 0.f, 0.f);
    float run_e = 0.f, run_m = 0.f;     // valid t<16

    // ---- prefetch tile 0 ----
    {
        float* dst = sm + SX0;
        const float4* src = xb + (size_t)tile0 * (TILE / 4);
        #pragma unroll
        for (int it = 0; it < 4; ++it) {
            int c = it * 64 + cg;
            cp16(dst + c * TILE + q * 4, src + (size_t)c * (HW_ / 4) + q);
        }
        CP_COMMIT();
    }

    for (int sub = 0; sub < SUBT; ++sub) {
        float* cur = sm + ((sub & 1) ? SX1 : SX0);
        if (sub + 1 < SUBT) {
            float* dst = sm + (((sub + 1) & 1) ? SX1 : SX0);
            const float4* src = xb + (size_t)(tile0 + sub + 1) * (TILE / 4);
            #pragma unroll
            for (int it = 0; it < 4; ++it) {
                int c = it * 64 + cg;
                cp16(dst + c * TILE + q * 4, src + (size_t)c * (HW_ / 4) + q);
            }
            CP_COMMIT();
            CP_WAIT(1);
        } else {
            CP_WAIT(0);
        }
        __syncthreads();

        // ---- phase2: logit & max partials (4 channels x 4 positions per thread),
        //      channel rotation (i+cg)&3 keeps LDS.128 conflict-free ----
        {
            float4 lp = make_float4(0.f, 0.f, 0.f, 0.f);
            float4 mp = make_float4(-1e30f, -1e30f, -1e30f, -1e30f);
            #pragma unroll
            for (int i = 0; i < 4; ++i) {
                const int ii = (i + cg) & 3;
                const float4 v = *reinterpret_cast<const float4*>(cur + (cg * 4 + ii) * TILE + q * 4);
                const float wc = wreg[ii];
                lp.x = fmaf(v.x, wc, lp.x); lp.y = fmaf(v.y, wc, lp.y);
                lp.z = fmaf(v.z, wc, lp.z); lp.w = fmaf(v.w, wc, lp.w);
                mp.x = fmaxf(mp.x, v.x);    mp.y = fmaxf(mp.y, v.y);
                mp.z = fmaxf(mp.z, v.z);    mp.w = fmaxf(mp.w, v.w);
            }
            // warp-level reduce over the 8 channel-groups (lanes stride 4, same q)
            #pragma unroll
            for (int off = 4; off < 32; off <<= 1) {
                lp.x += __shfl_down_sync(0xffffffffu, lp.x, off);
                lp.y += __shfl_down_sync(0xffffffffu, lp.y, off);
                lp.z += __shfl_down_sync(0xffffffffu, lp.z, off);
                lp.w += __shfl_down_sync(0xffffffffu, lp.w, off);
                mp.x = fmaxf(mp.x, __shfl_down_sync(0xffffffffu, mp.x, off));
                mp.y = fmaxf(mp.y, __shfl_down_sync(0xffffffffu, mp.y, off));
                mp.z = fmaxf(mp.z, __shfl_down_sync(0xffffffffu, mp.z, off));
                mp.w = fmaxf(mp.w, __shfl_down_sync(0xffffffffu, mp.w, off));
            }
            if (lane < 4) {
                *reinterpret_cast<float4*>(sm + AL + wp * TILE + lane * 4) = lp;
                *reinterpret_cast<float4*>(sm + AM + wp * TILE + lane * 4) = mp;
            }
        }
        __syncthreads();

        // ---- combine: threads 0..15, one position each ----
        if (t < TILE) {
            float l = bm, m = -1e30f;
            #pragma unroll
            for (int p = 0; p < 8; ++p) {
                l += sm[AL + p * TILE + t];
                m  = fmaxf(m, sm[AM + p * TILE + t]);
            }
            float e = __expf(l);      // unnormalized softmax weight (logits O(3))
            sm[SE + t] = e;
            run_e += e;
            run_m += m;
        }
        __syncthreads();

        // ---- phase3: per-channel accumulation, quad rotation (t>>1)&3 -> conflict-free ----
        {
            const int rot = (t >> 1) & 3;
            #pragma unroll
            for (int q2 = 0; q2 < 4; ++q2) {
                const int jj = (q2 + rot) & 3;
                const float4 v = *reinterpret_cast<const float4*>(cur + t * TILE + jj * 4);
                const float4 e = *reinterpret_cast<const float4*>(sm + SE + jj * 4);
                sv.x += v.x; sv.y += v.y; sv.z += v.z; sv.w += v.w;
                sve.x = fmaf(v.x, e.x, sve.x); sve.y = fmaf(v.y, e.y, sve.y);
                sve.z = fmaf(v.z, e.z, sve.z); sve.w = fmaf(v.w, e.w, sve.w);
            }
        }
        __syncthreads();   // buffer + se reuse barrier
    }

    // ---- global accumulation ----
    atomicAdd(&g_sumc[b * C_ + t], (sv.x + sv.y) + (sv.z + sv.w));
    atomicAdd(&g_num [b * C_ + t], (sve.x + sve.y) + (sve.z + sve.w));
    {
        // lanes >=16 hold zeros; plain sum reduction is correct for both
        #pragma unroll
        for (int off = 16; off > 0; off >>= 1) {
            run_e += __shfl_down_sync(0xffffffffu, run_e, off);
            run_m += __shfl_down_sync(0xffffffffu, run_m, off);
        }
        if (t == 0) { atomicAdd(&g_D[b], run_e); atomicAdd(&g_summ[b], run_m); }
    }
    __threadfence();
    __syncthreads();
    if (t == 0) {
        unsigned old = atomicAdd(&g_cnt[b], 1u);
        s_last = (old == NBLK - 1);
    }
    __syncthreads();
    if (!s_last) return;

    // ================= finalize (last CTA of this batch) =================
    float* ctx   = sm;            // 256
    float* bcv   = sm + 256;      // 256
    float* tvs   = sm + 512;      // 128
    float* tg    = sm + 640;      // 128
    float* sout  = sm + 768;      // 256
    float* red_s = sm + 1024;     // 4
    float* red_q = sm + 1028;     // 4
    float* red_a = sm + 1032;     // 8
    float* hid   = sm + 1040;     // 16
    float* o8    = sm + 1056;     // 8
    float* kar   = sm + 1064;     // 4
    float* fvv   = sm + 1072;     // 8
    float* shm   = sm + 1080;     // 1

    const float Dv    = __ldcg(&g_D[b]);
    const float summv = __ldcg(&g_summ[b]);
    const float numv  = __ldcg(&g_num [b * C_ + t]);
    const float sumcv = __ldcg(&g_sumc[b * C_ + t]);

    // re-zero scratch for next graph replay (this CTA is the only remaining reader)
    g_num [b * C_ + t] = 0.f;
    g_sumc[b * C_ + t] = 0.f;
    if (t == 0) { g_D[b] = 0.f; g_summ[b] = 0.f; g_cnt[b] = 0u; shm[0] = summv * (1.f / (float)HW_); }

    ctx[t] = numv  * (1.f / Dv);
    bcv[t] = sumcv * (1.f / (float)HW_);
    {
        float s = sumcv * (1.f / (float)HW_);
        #pragma unroll
        for (int off = 16; off > 0; off >>= 1) s += __shfl_down_sync(0xffffffffu, s, off);
        if (lane == 0) red_a[wp] = s;
    }
    __syncthreads();

    const float aval = (red_a[0] + red_a[1] + red_a[2] + red_a[3] +
                        red_a[4] + red_a[5] + red_a[6] + red_a[7]) * (1.f / (float)C_);
    const float mv = shm[0];

    // conv1 (128x256): warp wp -> planes wp*16..+15
    {
        const float4* ctx4 = reinterpret_cast<const float4*>(ctx);
        const float4 c0 = ctx4[lane];
        const float4 c1 = ctx4[lane + 32];
        #pragma unroll 4
        for (int i = 0; i < 16; ++i) {
            int p = wp * 16 + i;
            const float4* w4 = reinterpret_cast<const float4*>(w_cm1 + p * C_);
            float4 a0 = w4[lane];
            float4 a1 = w4[lane + 32];
            float pr = a0.x * c0.x + a0.y * c0.y + a0.z * c0.z + a0.w * c0.w
                     + a1.x * c1.x + a1.y * c1.y + a1.z * c1.z + a1.w * c1.w;
            #pragma unroll
            for (int off = 16; off > 0; off >>= 1)
                pr += __shfl_down_sync(0xffffffffu, pr, off);
            if (lane == 0) tvs[p] = pr + b_cm1[p];
        }
    }
    __syncthreads();

    // LayerNorm(128) + exact GELU
    {
        float tvv = (t < PLANES) ? tvs[t] : 0.f;
        float s1 = tvv, s2 = tvv * tvv;
        #pragma unroll
        for (int off = 16; off > 0; off >>= 1) {
            s1 += __shfl_down_sync(0xffffffffu, s1, off);
            s2 += __shfl_down_sync(0xffffffffu, s2, off);
        }
        if (t < PLANES && lane == 0) { red_s[wp] = s1; red_q[wp] = s2; }
        __syncthreads();
        if (t < PLANES) {
            float S  = red_s[0] + red_s[1] + red_s[2] + red_s[3];
            float SQ = red_q[0] + red_q[1] + red_q[2] + red_q[3];
            float mu  = S * (1.f / PLANES);
            float var = SQ * (1.f / PLANES) - mu * mu;
            float tn = (tvv - mu) * rsqrtf(var + EPS_) * ln_w[t] + ln_b[t];
            tg[t] = 0.5f * tn * (1.f + erff(tn * 0.70710678118654752f));
        }
    }
    __syncthreads();

    // conv2 (256x128): warp wp -> channels wp*32..+31
    {
        const float4* tg4 = reinterpret_cast<const float4*>(tg);
        const float4 g0 = tg4[lane];
        #pragma unroll 4
        for (int i = 0; i < 32; ++i) {
            int ch = wp * 32 + i;
            const float4* w4 = reinterpret_cast<const float4*>(w_cm2 + ch * PLANES);
            float4 a0 = w4[lane];
            float pr = a0.x * g0.x + a0.y * g0.y + a0.z * g0.z + a0.w * g0.w;
            #pragma unroll
            for (int off = 16; off > 0; off >>= 1)
                pr += __shfl_down_sync(0xffffffffu, pr, off);
            if (lane == 0)
                sout[ch] = bcv[ch] + pr + b_cm2[ch] + ((ch & 1) ? mv : aval);
        }
    }
    __syncthreads();

    // net1 (16x256): warp wp -> hidden wp*2, wp*2+1
    {
        const float4* so4 = reinterpret_cast<const float4*>(sout);
        const float4 s0 = so4[lane];
        const float4 s1v = so4[lane + 32];
        #pragma unroll
        for (int j = 0; j < 2; ++j) {
            int hh = wp * 2 + j;
            const float4* w4 = reinterpret_cast<const float4*>(w_net1 + hh * C_);
            float4 a0 = w4[lane];
            float4 a1 = w4[lane + 32];
            float pr = a0.x * s0.x + a0.y * s0.y + a0.z * s0.z + a0.w * s0.w
                     + a1.x * s1v.x + a1.y * s1v.y + a1.z * s1v.z + a1.w * s1v.w;
            #pragma unroll
            for (int off = 16; off > 0; off >>= 1)
                pr += __shfl_down_sync(0xffffffffu, pr, off);
            if (lane == 0) hid[hh] = fmaxf(pr, 0.f);
        }
    }
    __syncthreads();

    if (t < K_) {
        float o = 0.f;
        #pragma unroll
        for (int q2 = 0; q2 < HIDDEN; ++q2) o = fmaf(hid[q2], w_net2[t * HIDDEN + q2], o);
        o8[t] = o;
    }
    __syncthreads();
    if (t < ATT_CH) {
        float ka = 0.f;
        #pragma unroll
        for (int k = 0; k < K_; ++k) ka = fmaf(o8[k], w_fc[t * K_ + k], ka);
        ka = (ka - bn_mean[t]) * rsqrtf(bn_var[t] + EPS_) * bn_w[t] + bn_b[t];
        kar[t] = fmaxf(ka, 0.f);
    }
    __syncthreads();
    if (t < K_) {
        float kk = 0.f;
        #pragma unroll
        for (int q2 = 0; q2 < ATT_CH; ++q2) kk = fmaf(kar[q2], w_kfc[t * ATT_CH + q2], kk);
        float ker = 1.f / (1.f + __expf(-kk));
        fvv[t] = o8[t] * ker * (1.f / 30.f);
    }
    __syncthreads();
    if (t == 0) {
        float mx = -1e30f;
        #pragma unroll
        for (int k = 0; k < K_; ++k) mx = fmaxf(mx, fvv[k]);
        float e[K_], s = 0.f;
        #pragma unroll
        for (int k = 0; k < K_; ++k) { e[k] = __expf(fvv[k] - mx); s += e[k]; }
        float inv = 1.f / s;
        #pragma unroll
        for (int k = 0; k < K_; ++k) out[b * K_ + k] = e[k] * inv;
    }
}

// ---------------- launch ----------------
extern "C" void kernel_launch(void* const* d_in, const int* in_sizes, int n_in,
                              void* d_out, int out_size) {
    const float* x      = (const float*)d_in[0];
    const float* w_mask = (const float*)d_in[1];
    const float* b_mask = (const float*)d_in[2];
    const float* w_cm1  = (const float*)d_in[3];
    const float* b_cm1  = (const float*)d_in[4];
    const float* ln_w   = (const float*)d_in[5];
    const float* ln_b   = (const float*)d_in[6];
    const float* w_cm2  = (const float*)d_in[7];
    const float* b_cm2  = (const float*)d_in[8];
    const float* w_net1 = (const float*)d_in[9];
    const float* w_net2 = (const float*)d_in[10];
    const float* w_fc   = (const float*)d_in[11];
    const float* bn_w   = (const float*)d_in[12];
    const float* bn_b   = (const float*)d_in[13];
    const float* bn_mean= (const float*)d_in[14];
    const float* bn_var = (const float*)d_in[15];
    const float* w_kfc  = (const float*)d_in[16];
    float* out = (float*)d_out;

    fused<<<B_ * NBLK, 256, SMEM_BYTES>>>(x, w_mask, b_mask,
                          w_cm1, b_cm1, ln_w, ln_b, w_cm2, b_cm2,
                          w_net1, w_net2, w_fc, bn_w, bn_b, bn_mean, bn_var,
                          w_kfc, out);
}

// round 6
// speedup vs baseline: 1.4514x; 1.4514x over previous
#include <cuda_runtime.h>
#include <math.h>

// ---------------- problem constants ----------------
#define B_   64
#define C_   256
#define HW_  4096            // 64*64
#define TILE 32              // spatial positions per tile
#define SUBT 8               // tiles per CTA
#define NBLK 16              // CTAs per batch  (16*8*32 = 4096)
#define PLANES 128
#define HIDDEN 16
#define K_   8
#define ATT_CH 4
#define EPS_ 1e-5f

typedef unsigned long long u64;

// ---------------- device scratch (zero-init at load; last CTA re-zeros) ----------------
__device__ float    g_sumc[B_ * C_];
__device__ float    g_num [B_ * C_];
__device__ float    g_D   [B_];
__device__ float    g_summ[B_];
__device__ unsigned g_cnt [B_];

// ---------------- dynamic smem layout (float indices) ----------------
#define SX0  0                 // 8192 f (32 KB) tile buffer 0, row stride 32
#define SX1  8192              // 8192 f         tile buffer 1
#define AL   16384             // 256 f  logit partials [8 warp][32 pos]
#define AM   (16384 + 256)     // 256 f  max partials
#define SE   (16384 + 512)     // 256 f  exp weights  [8 warp][32 pos]
#define WD   (16384 + 768)     // 512 f  = 256 u64 packed mask weights
#define SMEM_FLOATS (16384 + 768 + 512)
#define SMEM_BYTES  (SMEM_FLOATS * 4)    // 70656 B -> 3 CTAs/SM

// ---------------- helpers ----------------
__device__ __forceinline__ void cp16(float* s, const float4* g) {
    unsigned sa = (unsigned)__cvta_generic_to_shared(s);
    asm volatile("cp.async.cg.shared.global [%0], [%1], 16;\n" :: "r"(sa), "l"(g));
}
#define CP_COMMIT()  asm volatile("cp.async.commit_group;\n")
#define CP_WAIT0()   asm volatile("cp.async.wait_group 0;\n")

__device__ __forceinline__ u64 pk(float a, float b) {
    u64 u; asm("mov.b64 %0, {%1, %2};" : "=l"(u) : "f"(a), "f"(b)); return u;
}
__device__ __forceinline__ void upk(u64 u, float& a, float& b) {
    asm("mov.b64 {%0, %1}, %2;" : "=f"(a), "=f"(b) : "l"(u));
}
__device__ __forceinline__ void fma2(u64& d, u64 a, u64 b) {
    asm("fma.rn.f32x2 %0, %1, %2, %0;" : "+l"(d) : "l"(a), "l"(b));
}
__device__ __forceinline__ void add2(u64& d, u64 a) {
    asm("add.rn.f32x2 %0, %1, %0;" : "+l"(d) : "l"(a));
}

__global__ __launch_bounds__(256, 3) void fused(
        const float* __restrict__ x,
        const float* __restrict__ w_mask, const float* __restrict__ b_mask,
        const float* __restrict__ w_cm1, const float* __restrict__ b_cm1,
        const float* __restrict__ ln_w,  const float* __restrict__ ln_b,
        const float* __restrict__ w_cm2, const float* __restrict__ b_cm2,
        const float* __restrict__ w_net1, const float* __restrict__ w_net2,
        const float* __restrict__ w_fc,
        const float* __restrict__ bn_w,  const float* __restrict__ bn_b,
        const float* __restrict__ bn_mean, const float* __restrict__ bn_var,
        const float* __restrict__ w_kfc,
        float* __restrict__ out) {
    extern __shared__ __align__(16) float sm[];
    __shared__ int s_last;

    const int t    = threadIdx.x;    // 0..255
    const int lane = t & 31;
    const int w    = t >> 5;
    const int b    = blockIdx.x >> 4;
    const int blk  = blockIdx.x & (NBLK - 1);
    const int tile0 = blk * SUBT;

    const int cg = t >> 3;           // channel group 0..31 (8 channels: cg*8+i)
    const int q  = t & 7;            // position quad: positions q*4..q*4+3

    // packed (duplicated) mask weights in smem: swd[c] = {w[c], w[c]}
    u64* swd = reinterpret_cast<u64*>(sm + WD);
    swd[t] = pk(w_mask[t], w_mask[t]);
    const float bm = b_mask[0];

    const float4* xb = reinterpret_cast<const float4*>(x) + (size_t)b * C_ * (HW_ / 4);

    // accumulators across tiles
    float sv[8];                     // channel sums (this thread's 8 ch, its 4 pos)
    u64   pacc[8];                   // packed weighted sums
    #pragma unroll
    for (int i = 0; i < 8; ++i) { sv[i] = 0.f; pacc[i] = 0ull; }
    float re = 0.f, rm = 0.f;        // warp 0 only

    // ---- prefetch tile 0 (coalesced: 4 channel rows per warp-instr, nL=4) ----
    {
        float* dst = sm + SX0;
        const float4* src = xb + (size_t)tile0 * 8;
        #pragma unroll
        for (int it = 0; it < 8; ++it) {
            int c = it * 32 + w * 4 + (lane >> 3);
            cp16(dst + c * 32 + (lane & 7) * 4, src + (size_t)c * (HW_ / 4) + (lane & 7));
        }
        CP_COMMIT();
    }

    for (int sub = 0; sub < SUBT; ++sub) {
        float* cur = sm + ((sub & 1) ? SX1 : SX0);
        CP_WAIT0();
        __syncthreads();                          // S1: tile ready, prev phases done

        if (sub + 1 < SUBT) {                     // prefetch next into other buffer
            float* dst = sm + ((sub & 1) ? SX0 : SX1);
            const float4* src = xb + (size_t)(tile0 + sub + 1) * 8;
            #pragma unroll
            for (int it = 0; it < 8; ++it) {
                int c = it * 32 + w * 4 + (lane >> 3);
                cp16(dst + c * 32 + (lane & 7) * 4, src + (size_t)c * (HW_ / 4) + (lane & 7));
            }
            CP_COMMIT();
        }

        // ---- phase2: load 8ch x 4pos into regs; logit/max/sum ----
        u64 d0[8], d1[8];
        u64 l01 = 0ull, l23 = 0ull;
        float m0 = -1e30f, m1 = -1e30f, m2 = -1e30f, m3 = -1e30f;
        #pragma unroll
        for (int i = 0; i < 8; ++i) {
            const ulonglong2 u = *reinterpret_cast<const ulonglong2*>(cur + (cg * 8 + i) * 32 + q * 4);
            d0[i] = u.x; d1[i] = u.y;
            const u64 wv = swd[cg * 8 + i];
            fma2(l01, u.x, wv);
            fma2(l23, u.y, wv);
            float f0, f1, f2, f3; upk(u.x, f0, f1); upk(u.y, f2, f3);
            m0 = fmaxf(m0, f0); m1 = fmaxf(m1, f1); m2 = fmaxf(m2, f2); m3 = fmaxf(m3, f3);
            sv[i] += (f0 + f1) + (f2 + f3);
        }
        // reduce over the 4 cg-groups within the warp (lanes stride 8)
        #pragma unroll
        for (int off = 8; off <= 16; off <<= 1) {
            u64 a = __shfl_down_sync(0xffffffffu, l01, off); add2(l01, a);
            u64 c2 = __shfl_down_sync(0xffffffffu, l23, off); add2(l23, c2);
            m0 = fmaxf(m0, __shfl_down_sync(0xffffffffu, m0, off));
            m1 = fmaxf(m1, __shfl_down_sync(0xffffffffu, m1, off));
            m2 = fmaxf(m2, __shfl_down_sync(0xffffffffu, m2, off));
            m3 = fmaxf(m3, __shfl_down_sync(0xffffffffu, m3, off));
        }
        if (lane < 8) {
            ulonglong2 lo; lo.x = l01; lo.y = l23;
            *reinterpret_cast<ulonglong2*>(sm + AL + w * 32 + lane * 4) = lo;
            float4 mv4 = make_float4(m0, m1, m2, m3);
            *reinterpret_cast<float4*>(sm + AM + w * 32 + lane * 4) = mv4;
        }
        __syncthreads();                          // S2: partials visible

        // ---- self-combine (every warp, lane = position) ----
        {
            float l = bm;
            #pragma unroll
            for (int p = 0; p < 8; ++p) l += sm[AL + p * 32 + lane];
            float e = __expf(l);                  // unnormalized softmax weight
            sm[SE + w * 32 + lane] = e;
            if (w == 0) {
                re += e;
                float m = -1e30f;
                #pragma unroll
                for (int p = 0; p < 8; ++p) m = fmaxf(m, sm[AM + p * 32 + lane]);
                rm += m;
            }
        }
        __syncwarp();

        // ---- phase3: weighted accumulate from registers (no tile re-read) ----
        {
            const ulonglong2 eu = *reinterpret_cast<const ulonglong2*>(sm + SE + w * 32 + q * 4);
            #pragma unroll
            for (int i = 0; i < 8; ++i) {
                fma2(pacc[i], d0[i], eu.x);
                fma2(pacc[i], d1[i], eu.y);
            }
        }
    }

    // ---- end-of-loop reductions: over the 8 q-lanes per channel group ----
    float sve[8];
    #pragma unroll
    for (int i = 0; i < 8; ++i) { float lo, hi; upk(pacc[i], lo, hi); sve[i] = lo + hi; }
    #pragma unroll
    for (int off = 4; off > 0; off >>= 1) {
        #pragma unroll
        for (int i = 0; i < 8; ++i) {
            sv[i]  += __shfl_down_sync(0xffffffffu, sv[i],  off, 8);
            sve[i] += __shfl_down_sync(0xffffffffu, sve[i], off, 8);
        }
    }
    if (q == 0) {
        #pragma unroll
        for (int i = 0; i < 8; ++i) {
            atomicAdd(&g_sumc[b * C_ + cg * 8 + i], sv[i]);
            atomicAdd(&g_num [b * C_ + cg * 8 + i], sve[i]);
        }
    }
    if (w == 0) {
        #pragma unroll
        for (int off = 16; off > 0; off >>= 1) {
            re += __shfl_down_sync(0xffffffffu, re, off);
            rm += __shfl_down_sync(0xffffffffu, rm, off);
        }
        if (lane == 0) { atomicAdd(&g_D[b], re); atomicAdd(&g_summ[b], rm); }
    }
    __threadfence();
    __syncthreads();
    if (t == 0) {
        unsigned old = atomicAdd(&g_cnt[b], 1u);
        s_last = (old == NBLK - 1);
    }
    __syncthreads();
    if (!s_last) return;

    // ================= finalize (last CTA of this batch) =================
    float* ctx   = sm;            // 256
    float* bcv   = sm + 256;      // 256
    float* tvs   = sm + 512;      // 128
    float* tg    = sm + 640;      // 128
    float* sout  = sm + 768;      // 256
    float* red_s = sm + 1024;     // 4
    float* red_q = sm + 1028;     // 4
    float* red_a = sm + 1032;     // 8
    float* hid   = sm + 1040;     // 16
    float* o8    = sm + 1056;     // 8
    float* kar   = sm + 1064;     // 4
    float* fvv   = sm + 1072;     // 8
    float* shm   = sm + 1080;     // 1

    const int wp = w;

    const float Dv    = __ldcg(&g_D[b]);
    const float summv = __ldcg(&g_summ[b]);
    const float numv  = __ldcg(&g_num [b * C_ + t]);
    const float sumcv = __ldcg(&g_sumc[b * C_ + t]);

    // re-zero scratch for next graph replay (this CTA is the only remaining reader)
    g_num [b * C_ + t] = 0.f;
    g_sumc[b * C_ + t] = 0.f;
    if (t == 0) { g_D[b] = 0.f; g_summ[b] = 0.f; g_cnt[b] = 0u; shm[0] = summv * (1.f / (float)HW_); }

    ctx[t] = numv  * (1.f / Dv);
    bcv[t] = sumcv * (1.f / (float)HW_);
    {
        float s = sumcv * (1.f / (float)HW_);
        #pragma unroll
        for (int off = 16; off > 0; off >>= 1) s += __shfl_down_sync(0xffffffffu, s, off);
        if (lane == 0) red_a[wp] = s;
    }
    __syncthreads();

    const float aval = (red_a[0] + red_a[1] + red_a[2] + red_a[3] +
                        red_a[4] + red_a[5] + red_a[6] + red_a[7]) * (1.f / (float)C_);
    const float mv = shm[0];

    // conv1 (128x256): warp wp -> planes wp*16..+15
    {
        const float4* ctx4 = reinterpret_cast<const float4*>(ctx);
        const float4 c0 = ctx4[lane];
        const float4 c1 = ctx4[lane + 32];
        #pragma unroll 4
        for (int i = 0; i < 16; ++i) {
            int p = wp * 16 + i;
            const float4* w4 = reinterpret_cast<const float4*>(w_cm1 + p * C_);
            float4 a0 = w4[lane];
            float4 a1 = w4[lane + 32];
            float pr = a0.x * c0.x + a0.y * c0.y + a0.z * c0.z + a0.w * c0.w
                     + a1.x * c1.x + a1.y * c1.y + a1.z * c1.z + a1.w * c1.w;
            #pragma unroll
            for (int off = 16; off > 0; off >>= 1)
                pr += __shfl_down_sync(0xffffffffu, pr, off);
            if (lane == 0) tvs[p] = pr + b_cm1[p];
        }
    }
    __syncthreads();

    // LayerNorm(128) + exact GELU
    {
        float tvv = (t < PLANES) ? tvs[t] : 0.f;
        float s1 = tvv, s2 = tvv * tvv;
        #pragma unroll
        for (int off = 16; off > 0; off >>= 1) {
            s1 += __shfl_down_sync(0xffffffffu, s1, off);
            s2 += __shfl_down_sync(0xffffffffu, s2, off);
        }
        if (t < PLANES && lane == 0) { red_s[wp] = s1; red_q[wp] = s2; }
        __syncthreads();
        if (t < PLANES) {
            float S  = red_s[0] + red_s[1] + red_s[2] + red_s[3];
            float SQ = red_q[0] + red_q[1] + red_q[2] + red_q[3];
            float mu  = S * (1.f / PLANES);
            float var = SQ * (1.f / PLANES) - mu * mu;
            float tn = (tvv - mu) * rsqrtf(var + EPS_) * ln_w[t] + ln_b[t];
            tg[t] = 0.5f * tn * (1.f + erff(tn * 0.70710678118654752f));
        }
    }
    __syncthreads();

    // conv2 (256x128): warp wp -> channels wp*32..+31
    {
        const float4* tg4 = reinterpret_cast<const float4*>(tg);
        const float4 g0 = tg4[lane];
        #pragma unroll 4
        for (int i = 0; i < 32; ++i) {
            int ch = wp * 32 + i;
            const float4* w4 = reinterpret_cast<const float4*>(w_cm2 + ch * PLANES);
            float4 a0 = w4[lane];
            float pr = a0.x * g0.x + a0.y * g0.y + a0.z * g0.z + a0.w * g0.w;
            #pragma unroll
            for (int off = 16; off > 0; off >>= 1)
                pr += __shfl_down_sync(0xffffffffu, pr, off);
            if (lane == 0)
                sout[ch] = bcv[ch] + pr + b_cm2[ch] + ((ch & 1) ? mv : aval);
        }
    }
    __syncthreads();

    // net1 (16x256): warp wp -> hidden wp*2, wp*2+1
    {
        const float4* so4 = reinterpret_cast<const float4*>(sout);
        const float4 s0 = so4[lane];
        const float4 s1v = so4[lane + 32];
        #pragma unroll
        for (int j = 0; j < 2; ++j) {
            int hh = wp * 2 + j;
            const float4* w4 = reinterpret_cast<const float4*>(w_net1 + hh * C_);
            float4 a0 = w4[lane];
            float4 a1 = w4[lane + 32];
            float pr = a0.x * s0.x + a0.y * s0.y + a0.z * s0.z + a0.w * s0.w
                     + a1.x * s1v.x + a1.y * s1v.y + a1.z * s1v.z + a1.w * s1v.w;
            #pragma unroll
            for (int off = 16; off > 0; off >>= 1)
                pr += __shfl_down_sync(0xffffffffu, pr, off);
            if (lane == 0) hid[hh] = fmaxf(pr, 0.f);
        }
    }
    __syncthreads();

    if (t < K_) {
        float o = 0.f;
        #pragma unroll
        for (int q2 = 0; q2 < HIDDEN; ++q2) o = fmaf(hid[q2], w_net2[t * HIDDEN + q2], o);
        o8[t] = o;
    }
    __syncthreads();
    if (t < ATT_CH) {
        float ka = 0.f;
        #pragma unroll
        for (int k = 0; k < K_; ++k) ka = fmaf(o8[k], w_fc[t * K_ + k], ka);
        ka = (ka - bn_mean[t]) * rsqrtf(bn_var[t] + EPS_) * bn_w[t] + bn_b[t];
        kar[t] = fmaxf(ka, 0.f);
    }
    __syncthreads();
    if (t < K_) {
        float kk = 0.f;
        #pragma unroll
        for (int q2 = 0; q2 < ATT_CH; ++q2) kk = fmaf(kar[q2], w_kfc[t * ATT_CH + q2], kk);
        float ker = 1.f / (1.f + __expf(-kk));
        fvv[t] = o8[t] * ker * (1.f / 30.f);
    }
    __syncthreads();
    if (t == 0) {
        float mx = -1e30f;
        #pragma unroll
        for (int k = 0; k < K_; ++k) mx = fmaxf(mx, fvv[k]);
        float e[K_], s = 0.f;
        #pragma unroll
        for (int k = 0; k < K_; ++k) { e[k] = __expf(fvv[k] - mx); s += e[k]; }
        float inv = 1.f / s;
        #pragma unroll
        for (int k = 0; k < K_; ++k) out[b * K_ + k] = e[k] * inv;
    }
}

// ---------------- launch ----------------
extern "C" void kernel_launch(void* const* d_in, const int* in_sizes, int n_in,
                              void* d_out, int out_size) {
    const float* x      = (const float*)d_in[0];
    const float* w_mask = (const float*)d_in[1];
    const float* b_mask = (const float*)d_in[2];
    const float* w_cm1  = (const float*)d_in[3];
    const float* b_cm1  = (const float*)d_in[4];
    const float* ln_w   = (const float*)d_in[5];
    const float* ln_b   = (const float*)d_in[6];
    const float* w_cm2  = (const float*)d_in[7];
    const float* b_cm2  = (const float*)d_in[8];
    const float* w_net1 = (const float*)d_in[9];
    const float* w_net2 = (const float*)d_in[10];
    const float* w_fc   = (const float*)d_in[11];
    const float* bn_w   = (const float*)d_in[12];
    const float* bn_b   = (const float*)d_in[13];
    const float* bn_mean= (const float*)d_in[14];
    const float* bn_var = (const float*)d_in[15];
    const float* w_kfc  = (const float*)d_in[16];
    float* out = (float*)d_out;

    static bool configured = false;
    if (!configured) {
        cudaFuncSetAttribute(fused, cudaFuncAttributeMaxDynamicSharedMemorySize, SMEM_BYTES);
        configured = true;
    }
    fused<<<B_ * NBLK, 256, SMEM_BYTES>>>(x, w_mask, b_mask,
                          w_cm1, b_cm1, ln_w, ln_b, w_cm2, b_cm2,
                          w_net1, w_net2, w_fc, bn_w, bn_b, bn_mean, bn_var,
                          w_kfc, out);
}

// round 8
// speedup vs baseline: 1.5150x; 1.0438x over previous
#include <cuda_runtime.h>
#include <math.h>

// ---------------- problem constants ----------------
#define B_   64
#define C_   256
#define HW_  4096            // 64*64
#define TILE 32              // spatial positions per tile
#define TPB_ 128             // tiles per batch
#define NBLK 7               // CTAs per batch -> grid 448 = one wave at 3 CTAs/SM
#define PLANES 128
#define HIDDEN 16
#define K_   8
#define ATT_CH 4
#define EPS_ 1e-5f

// ---------------- device scratch (zero-init at load; last CTA re-zeros) ----------------
__device__ float    g_sumc[B_ * C_];
__device__ float    g_num [B_ * C_];
__device__ float    g_D   [B_];
__device__ float    g_summ[B_];
__device__ unsigned g_cnt [B_];

// ---------------- dynamic smem layout (float indices) ----------------
#define SX0  0                 // 8192 f (32 KB) tile buffer 0, row stride 32
#define SX1  8192              // 8192 f        tile buffer 1
#define AL   16384             // 1024 f  logit partials [32 grp][32 pos]
#define AM   (16384 + 1024)    // 1024 f  max partials
#define SE   (16384 + 2048)    // 32 f    exp weights
#define SMEM_FLOATS (16384 + 2048 + 32)
#define SMEM_BYTES  (SMEM_FLOATS * 4)   // 73856 B -> 3 CTAs/SM

// ---------------- cp.async helpers ----------------
__device__ __forceinline__ void cp16(float* s, const float4* g) {
    unsigned sa = (unsigned)__cvta_generic_to_shared(s);
    asm volatile("cp.async.cg.shared.global [%0], [%1], 16;\n" :: "r"(sa), "l"(g));
}
#define CP_COMMIT()  asm volatile("cp.async.commit_group;\n")
#define CP_WAIT1()   asm volatile("cp.async.wait_group 1;\n")
#define CP_WAIT0()   asm volatile("cp.async.wait_group 0;\n")

__global__ __launch_bounds__(256) void fused(
        const float* __restrict__ x,
        const float* __restrict__ w_mask, const float* __restrict__ b_mask,
        const float* __restrict__ w_cm1, const float* __restrict__ b_cm1,
        const float* __restrict__ ln_w,  const float* __restrict__ ln_b,
        const float* __restrict__ w_cm2, const float* __restrict__ b_cm2,
        const float* __restrict__ w_net1, const float* __restrict__ w_net2,
        const float* __restrict__ w_fc,
        const float* __restrict__ bn_w,  const float* __restrict__ bn_b,
        const float* __restrict__ bn_mean, const float* __restrict__ bn_var,
        const float* __restrict__ w_kfc,
        float* __restrict__ out) {
    extern __shared__ __align__(16) float sm[];
    __shared__ int s_last;

    const int t    = threadIdx.x;    // 0..255
    const int lane = t & 31;
    const int w    = t >> 5;
    const int b    = blockIdx.x / NBLK;
    const int j    = blockIdx.x - b * NBLK;       // 0..6 within batch

    // tile range within this batch: 2 CTAs x 19 tiles + 5 CTAs x 18 tiles = 128
    const int my_count = (j < 2) ? 19 : 18;
    const int tile0    = (j < 2) ? j * 19 : 38 + (j - 2) * 18;

    const int cg = t >> 3;           // channel group 0..31 (8 channels)
    const int q  = t & 7;            // position quad 0..7

    // hoisted mask weights for this thread's 8 channels
    float4 wv0 = *reinterpret_cast<const float4*>(w_mask + cg * 8);
    float4 wv1 = *reinterpret_cast<const float4*>(w_mask + cg * 8 + 4);
    const float wreg[8] = {wv0.x, wv0.y, wv0.z, wv0.w, wv1.x, wv1.y, wv1.z, wv1.w};
    const float bm = b_mask[0];

    const float4* xb = reinterpret_cast<const float4*>(x) + (size_t)b * C_ * (HW_ / 4);

    // per-thread accumulators across tiles (channel = t)
    float4 sv  = make_float4(0.f, 0.f, 0.f, 0.f);
    float4 sve = make_float4(0.f, 0.f, 0.f, 0.f);
    float run_e = 0.f, run_m = 0.f;     // warp 0 lanes

    const int cl = w * 4 + (lane >> 3);   // channel row this lane loads (per it)
    const int ql = lane & 7;              // quad within row

    // ---- prefetch tile 0 ----
    {
        float* dst = sm + SX0;
        const float4* src = xb + (size_t)tile0 * 8;
        #pragma unroll
        for (int it = 0; it < 8; ++it) {
            int c = it * 32 + cl;
            cp16(dst + c * 32 + ql * 4, src + (size_t)c * (HW_ / 4) + ql);
        }
        CP_COMMIT();
    }

    for (int sub = 0; sub < my_count; ++sub) {
        float* cur = sm + ((sub & 1) ? SX1 : SX0);
        if (sub + 1 < my_count) {
            float* dst = sm + ((sub & 1) ? SX0 : SX1);
            const float4* src = xb + (size_t)(tile0 + sub + 1) * 8;
            #pragma unroll
            for (int it = 0; it < 8; ++it) {
                int c = it * 32 + cl;
                cp16(dst + c * 32 + ql * 4, src + (size_t)c * (HW_ / 4) + ql);
            }
            CP_COMMIT();
            CP_WAIT1();
        } else {
            CP_WAIT0();
        }
        __syncthreads();

        // ---- phase2: logit & max partials (8 ch x 4 pos per thread) ----
        {
            float4 lp = make_float4(0.f, 0.f, 0.f, 0.f);
            float4 mp = make_float4(-1e30f, -1e30f, -1e30f, -1e30f);
            #pragma unroll
            for (int i = 0; i < 8; ++i) {
                const float4 v = *reinterpret_cast<const float4*>(cur + (cg * 8 + i) * 32 + q * 4);
                const float wc = wreg[i];
                lp.x = fmaf(v.x, wc, lp.x); lp.y = fmaf(v.y, wc, lp.y);
                lp.z = fmaf(v.z, wc, lp.z); lp.w = fmaf(v.w, wc, lp.w);
                mp.x = fmaxf(mp.x, v.x);    mp.y = fmaxf(mp.y, v.y);
                mp.z = fmaxf(mp.z, v.z);    mp.w = fmaxf(mp.w, v.w);
            }
            *reinterpret_cast<float4*>(sm + AL + cg * 32 + q * 4) = lp;
            *reinterpret_cast<float4*>(sm + AM + cg * 32 + q * 4) = mp;
        }
        __syncthreads();

        // ---- combine: threads 0..31, one position each ----
        if (t < TILE) {
            float l = bm, m = -1e30f;
            #pragma unroll
            for (int p = 0; p < 32; ++p) {
                l += sm[AL + p * 32 + t];
                m  = fmaxf(m, sm[AM + p * 32 + t]);
            }
            float e = __expf(l);          // unnormalized softmax weight (logits O(3))
            sm[SE + t] = e;
            run_e += e;
            run_m += m;
        }
        __syncthreads();

        // ---- phase3: per-channel accumulation (thread t = channel t), rotated ----
        {
            const int rot = t & 7;
            #pragma unroll
            for (int q2 = 0; q2 < 8; ++q2) {
                const int jj = (q2 + rot) & 7;
                const float4 v = *reinterpret_cast<const float4*>(cur + t * 32 + jj * 4);
                const float4 e = *reinterpret_cast<const float4*>(sm + SE + jj * 4);
                sv.x += v.x; sv.y += v.y; sv.z += v.z; sv.w += v.w;
                sve.x = fmaf(v.x, e.x, sve.x); sve.y = fmaf(v.y, e.y, sve.y);
                sve.z = fmaf(v.z, e.z, sve.z); sve.w = fmaf(v.w, e.w, sve.w);
            }
        }
        __syncthreads();   // buffer + se reuse barrier
    }

    // ---- global accumulation ----
    atomicAdd(&g_sumc[b * C_ + t], (sv.x + sv.y) + (sv.z + sv.w));
    atomicAdd(&g_num [b * C_ + t], (sve.x + sve.y) + (sve.z + sve.w));
    if (w == 0) {
        #pragma unroll
        for (int off = 16; off > 0; off >>= 1) {
            run_e += __shfl_down_sync(0xffffffffu, run_e, off);
            run_m += __shfl_down_sync(0xffffffffu, run_m, off);
        }
        if (lane == 0) { atomicAdd(&g_D[b], run_e); atomicAdd(&g_summ[b], run_m); }
    }
    __threadfence();
    __syncthreads();
    if (t == 0) {
        unsigned old = atomicAdd(&g_cnt[b], 1u);
        s_last = (old == NBLK - 1);
    }
    __syncthreads();
    if (!s_last) return;

    // ================= finalize (last CTA of this batch; no cp.async in flight) =====
    float* ctx   = sm;            // 256
    float* bcv   = sm + 256;      // 256
    float* tvs   = sm + 512;      // 128
    float* tg    = sm + 640;      // 128
    float* sout  = sm + 768;      // 256
    float* red_s = sm + 1024;     // 4
    float* red_q = sm + 1028;     // 4
    float* red_a = sm + 1032;     // 8
    float* hid   = sm + 1040;     // 16
    float* o8    = sm + 1056;     // 8
    float* kar   = sm + 1064;     // 4
    float* fvv   = sm + 1072;     // 8
    float* shm   = sm + 1080;     // 1

    const int wp = w;

    const float Dv    = __ldcg(&g_D[b]);
    const float summv = __ldcg(&g_summ[b]);
    const float numv  = __ldcg(&g_num [b * C_ + t]);
    const float sumcv = __ldcg(&g_sumc[b * C_ + t]);

    // re-zero scratch for next graph replay (this CTA is the only remaining reader)
    g_num [b * C_ + t] = 0.f;
    g_sumc[b * C_ + t] = 0.f;
    if (t == 0) { g_D[b] = 0.f; g_summ[b] = 0.f; g_cnt[b] = 0u; shm[0] = summv * (1.f / (float)HW_); }

    ctx[t] = numv  * (1.f / Dv);
    bcv[t] = sumcv * (1.f / (float)HW_);
    {
        float s = sumcv * (1.f / (float)HW_);
        #pragma unroll
        for (int off = 16; off > 0; off >>= 1) s += __shfl_down_sync(0xffffffffu, s, off);
        if (lane == 0) red_a[wp] = s;
    }
    __syncthreads();

    const float aval = (red_a[0] + red_a[1] + red_a[2] + red_a[3] +
                        red_a[4] + red_a[5] + red_a[6] + red_a[7]) * (1.f / (float)C_);
    const float mv = shm[0];

    // conv1 (128x256): warp wp -> planes wp*16..+15
    {
        const float4* ctx4 = reinterpret_cast<const float4*>(ctx);
        const float4 c0 = ctx4[lane];
        const float4 c1 = ctx4[lane + 32];
        #pragma unroll 4
        for (int i = 0; i < 16; ++i) {
            int p = wp * 16 + i;
            const float4* w4 = reinterpret_cast<const float4*>(w_cm1 + p * C_);
            float4 a0 = w4[lane];
            float4 a1 = w4[lane + 32];
            float pr = a0.x * c0.x + a0.y * c0.y + a0.z * c0.z + a0.w * c0.w
                     + a1.x * c1.x + a1.y * c1.y + a1.z * c1.z + a1.w * c1.w;
            #pragma unroll
            for (int off = 16; off > 0; off >>= 1)
                pr += __shfl_down_sync(0xffffffffu, pr, off);
            if (lane == 0) tvs[p] = pr + b_cm1[p];
        }
    }
    __syncthreads();

    // LayerNorm(128) + exact GELU
    {
        float tvv = (t < PLANES) ? tvs[t] : 0.f;
        float s1 = tvv, s2 = tvv * tvv;
        #pragma unroll
        for (int off = 16; off > 0; off >>= 1) {
            s1 += __shfl_down_sync(0xffffffffu, s1, off);
            s2 += __shfl_down_sync(0xffffffffu, s2, off);
        }
        if (t < PLANES && lane == 0) { red_s[wp] = s1; red_q[wp] = s2; }
        __syncthreads();
        if (t < PLANES) {
            float S  = red_s[0] + red_s[1] + red_s[2] + red_s[3];
            float SQ = red_q[0] + red_q[1] + red_q[2] + red_q[3];
            float mu  = S * (1.f / PLANES);
            float var = SQ * (1.f / PLANES) - mu * mu;
            float tn = (tvv - mu) * rsqrtf(var + EPS_) * ln_w[t] + ln_b[t];
            tg[t] = 0.5f * tn * (1.f + erff(tn * 0.70710678118654752f));
        }
    }
    __syncthreads();

    // conv2 (256x128): warp wp -> channels wp*32..+31
    {
        const float4* tg4 = reinterpret_cast<const float4*>(tg);
        const float4 g0 = tg4[lane];
        #pragma unroll 4
        for (int i = 0; i < 32; ++i) {
            int ch = wp * 32 + i;
            const float4* w4 = reinterpret_cast<const float4*>(w_cm2 + ch * PLANES);
            float4 a0 = w4[lane];
            float pr = a0.x * g0.x + a0.y * g0.y + a0.z * g0.z + a0.w * g0.w;
            #pragma unroll
            for (int off = 16; off > 0; off >>= 1)
                pr += __shfl_down_sync(0xffffffffu, pr, off);
            if (lane == 0)
                sout[ch] = bcv[ch] + pr + b_cm2[ch] + ((ch & 1) ? mv : aval);
        }
    }
    __syncthreads();

    // net1 (16x256): warp wp -> hidden wp*2, wp*2+1
    {
        const float4* so4 = reinterpret_cast<const float4*>(sout);
        const float4 s0 = so4[lane];
        const float4 s1v = so4[lane + 32];
        #pragma unroll
        for (int jj = 0; jj < 2; ++jj) {
            int hh = wp * 2 + jj;
            const float4* w4 = reinterpret_cast<const float4*>(w_net1 + hh * C_);
            float4 a0 = w4[lane];
            float4 a1 = w4[lane + 32];
            float pr = a0.x * s0.x + a0.y * s0.y + a0.z * s0.z + a0.w * s0.w
                     + a1.x * s1v.x + a1.y * s1v.y + a1.z * s1v.z + a1.w * s1v.w;
            #pragma unroll
            for (int off = 16; off > 0; off >>= 1)
                pr += __shfl_down_sync(0xffffffffu, pr, off);
            if (lane == 0) hid[hh] = fmaxf(pr, 0.f);
        }
    }
    __syncthreads();

    if (t < K_) {
        float o = 0.f;
        #pragma unroll
        for (int q2 = 0; q2 < HIDDEN; ++q2) o = fmaf(hid[q2], w_net2[t * HIDDEN + q2], o);
        o8[t] = o;
    }
    __syncthreads();
    if (t < ATT_CH) {
        float ka = 0.f;
        #pragma unroll
        for (int k = 0; k < K_; ++k) ka = fmaf(o8[k], w_fc[t * K_ + k], ka);
        ka = (ka - bn_mean[t]) * rsqrtf(bn_var[t] + EPS_) * bn_w[t] + bn_b[t];
        kar[t] = fmaxf(ka, 0.f);
    }
    __syncthreads();
    if (t < K_) {
        float kk = 0.f;
        #pragma unroll
        for (int q2 = 0; q2 < ATT_CH; ++q2) kk = fmaf(kar[q2], w_kfc[t * ATT_CH + q2], kk);
        float ker = 1.f / (1.f + __expf(-kk));
        fvv[t] = o8[t] * ker * (1.f / 30.f);
    }
    __syncthreads();
    if (t == 0) {
        float mx = -1e30f;
        #pragma unroll
        for (int k = 0; k < K_; ++k) mx = fmaxf(mx, fvv[k]);
        float e[K_], s = 0.f;
        #pragma unroll
        for (int k = 0; k < K_; ++k) { e[k] = __expf(fvv[k] - mx); s += e[k]; }
        float inv = 1.f / s;
        #pragma unroll
        for (int k = 0; k < K_; ++k) out[b * K_ + k] = e[k] * inv;
    }
}

// ---------------- launch ----------------
extern "C" void kernel_launch(void* const* d_in, const int* in_sizes, int n_in,
                              void* d_out, int out_size) {
    const float* x      = (const float*)d_in[0];
    const float* w_mask = (const float*)d_in[1];
    const float* b_mask = (const float*)d_in[2];
    const float* w_cm1  = (const float*)d_in[3];
    const float* b_cm1  = (const float*)d_in[4];
    const float* ln_w   = (const float*)d_in[5];
    const float* ln_b   = (const float*)d_in[6];
    const float* w_cm2  = (const float*)d_in[7];
    const float* b_cm2  = (const float*)d_in[8];
    const float* w_net1 = (const float*)d_in[9];
    const float* w_net2 = (const float*)d_in[10];
    const float* w_fc   = (const float*)d_in[11];
    const float* bn_w   = (const float*)d_in[12];
    const float* bn_b   = (const float*)d_in[13];
    const float* bn_mean= (const float*)d_in[14];
    const float* bn_var = (const float*)d_in[15];
    const float* w_kfc  = (const float*)d_in[16];
    float* out = (float*)d_out;

    cudaFuncSetAttribute(fused, cudaFuncAttributeMaxDynamicSharedMemorySize, SMEM_BYTES);
    fused<<<B_ * NBLK, 256, SMEM_BYTES>>>(x, w_mask, b_mask,
                          w_cm1, b_cm1, ln_w, ln_b, w_cm2, b_cm2,
                          w_net1, w_net2, w_fc, bn_w, bn_b, bn_mean, bn_var,
                          w_kfc, out);
}

// round 9
// speedup vs baseline: 1.7553x; 1.1587x over previous
#include <cuda_runtime.h>
#include <math.h>

// ---------------- problem constants ----------------
#define B_   64
#define C_   256
#define HW_  4096            // 64*64
#define TILE 32              // spatial positions per tile
#define TPB_ 128             // tiles per batch
#define NBLK 7               // CTAs per batch -> grid 448 = one wave at 3 CTAs/SM
#define PLANES 128
#define HIDDEN 16
#define K_   8
#define ATT_CH 4
#define EPS_ 1e-5f

// ---------------- device scratch (zero-init at load; last CTA re-zeros) ----------------
__device__ float    g_sumc[B_ * C_];
__device__ float    g_num [B_ * C_];
__device__ float    g_D   [B_];
__device__ float    g_summ[B_];
__device__ unsigned g_cnt [B_];

__global__ __launch_bounds__(256, 3) void fused(
        const float* __restrict__ x,
        const float* __restrict__ w_mask, const float* __restrict__ b_mask,
        const float* __restrict__ w_cm1, const float* __restrict__ b_cm1,
        const float* __restrict__ ln_w,  const float* __restrict__ ln_b,
        const float* __restrict__ w_cm2, const float* __restrict__ b_cm2,
        const float* __restrict__ w_net1, const float* __restrict__ w_net2,
        const float* __restrict__ w_fc,
        const float* __restrict__ bn_w,  const float* __restrict__ bn_b,
        const float* __restrict__ bn_mean, const float* __restrict__ bn_var,
        const float* __restrict__ w_kfc,
        float* __restrict__ out) {
    // static smem: AL[8][32] + AM[8][32] partials; finalize reuses [0..1081)
    __shared__ __align__(16) float sm[1104];
    __shared__ int s_last;
    float* AL = sm;          // [8][32] logit partials
    float* AM = sm + 256;    // [8][32] max partials

    const int t    = threadIdx.x;    // 0..255
    const int lane = t & 31;
    const int w    = t >> 5;
    const int b    = blockIdx.x / NBLK;
    const int j    = blockIdx.x - b * NBLK;       // 0..6 within batch

    // tile range within this batch: 2 CTAs x 19 tiles + 5 CTAs x 18 tiles = 128
    const int my_count = (j < 2) ? 19 : 18;
    const int tile0    = (j < 2) ? j * 19 : 38 + (j - 2) * 18;

    const int cg = t >> 3;           // channel group 0..31 (channels cg*8+i)
    const int q  = t & 7;            // position quad 0..7 (positions 4q..4q+3)

    // hoisted mask weights for this thread's 8 channels
    float4 wv0 = *reinterpret_cast<const float4*>(w_mask + cg * 8);
    float4 wv1 = *reinterpret_cast<const float4*>(w_mask + cg * 8 + 4);
    const float wreg[8] = {wv0.x, wv0.y, wv0.z, wv0.w, wv1.x, wv1.y, wv1.z, wv1.w};
    const float bm = b_mask[0];

    const float4* xb = reinterpret_cast<const float4*>(x) + (size_t)b * C_ * (HW_ / 4)
                     + (size_t)(cg * 8) * (HW_ / 4) + q;

    // per-thread accumulators across tiles (channel cg*8+i, this thread's 4 positions)
    float sv[8], sve[8];
    #pragma unroll
    for (int i = 0; i < 8; ++i) { sv[i] = 0.f; sve[i] = 0.f; }
    float run_e = 0.f, run_m = 0.f;     // warp 0 lanes

    for (int sub = 0; sub < my_count; ++sub) {
        const float4* src = xb + (size_t)(tile0 + sub) * 8;

        // ---- load 8 channels x 4 positions straight to registers (coalesced LDG.128)
        float4 d[8];
        #pragma unroll
        for (int i = 0; i < 8; ++i) d[i] = __ldg(src + (size_t)i * (HW_ / 4));

        // ---- phase2: logit / max / channel-sum partials from registers
        float4 lp = make_float4(0.f, 0.f, 0.f, 0.f);
        float4 mp = make_float4(-1e30f, -1e30f, -1e30f, -1e30f);
        #pragma unroll
        for (int i = 0; i < 8; ++i) {
            const float wc = wreg[i];
            lp.x = fmaf(d[i].x, wc, lp.x); lp.y = fmaf(d[i].y, wc, lp.y);
            lp.z = fmaf(d[i].z, wc, lp.z); lp.w = fmaf(d[i].w, wc, lp.w);
            mp.x = fmaxf(mp.x, d[i].x);    mp.y = fmaxf(mp.y, d[i].y);
            mp.z = fmaxf(mp.z, d[i].z);    mp.w = fmaxf(mp.w, d[i].w);
            sv[i] += (d[i].x + d[i].y) + (d[i].z + d[i].w);
        }
        // intra-warp reduce over the 4 channel-groups (lanes stride 8, same q)
        #pragma unroll
        for (int off = 8; off <= 16; off <<= 1) {
            lp.x += __shfl_down_sync(0xffffffffu, lp.x, off);
            lp.y += __shfl_down_sync(0xffffffffu, lp.y, off);
            lp.z += __shfl_down_sync(0xffffffffu, lp.z, off);
            lp.w += __shfl_down_sync(0xffffffffu, lp.w, off);
            mp.x = fmaxf(mp.x, __shfl_down_sync(0xffffffffu, mp.x, off));
            mp.y = fmaxf(mp.y, __shfl_down_sync(0xffffffffu, mp.y, off));
            mp.z = fmaxf(mp.z, __shfl_down_sync(0xffffffffu, mp.z, off));
            mp.w = fmaxf(mp.w, __shfl_down_sync(0xffffffffu, mp.w, off));
        }
        __syncthreads();     // BAR A: previous tile's combine reads of AL/AM are done
        if (lane < 8) {
            *reinterpret_cast<float4*>(AL + w * 32 + lane * 4) = lp;
            *reinterpret_cast<float4*>(AM + w * 32 + lane * 4) = mp;
        }
        __syncthreads();     // BAR B: partials visible

        // ---- combine (every warp redundantly; lane = position) ----
        float l = bm;
        #pragma unroll
        for (int p = 0; p < 8; ++p) l += AL[p * 32 + lane];
        const float e = __expf(l);       // unnormalized softmax weight (logits O(3))
        if (w == 0) {
            run_e += e;
            float m = -1e30f;
            #pragma unroll
            for (int p = 0; p < 8; ++p) m = fmaxf(m, AM[p * 32 + lane]);
            run_m += m;
        }

        // ---- phase3: weighted accumulate from the SAME registers ----
        const float e0 = __shfl_sync(0xffffffffu, e, q * 4 + 0);
        const float e1 = __shfl_sync(0xffffffffu, e, q * 4 + 1);
        const float e2 = __shfl_sync(0xffffffffu, e, q * 4 + 2);
        const float e3 = __shfl_sync(0xffffffffu, e, q * 4 + 3);
        #pragma unroll
        for (int i = 0; i < 8; ++i) {
            float a = fmaf(d[i].x, e0, sve[i]);
            a = fmaf(d[i].y, e1, a);
            a = fmaf(d[i].z, e2, a);
            sve[i] = fmaf(d[i].w, e3, a);
        }
    }

    // ---- reduce sv/sve over the 8 q-lanes of each channel group ----
    #pragma unroll
    for (int off = 4; off > 0; off >>= 1) {
        #pragma unroll
        for (int i = 0; i < 8; ++i) {
            sv[i]  += __shfl_down_sync(0xffffffffu, sv[i],  off, 8);
            sve[i] += __shfl_down_sync(0xffffffffu, sve[i], off, 8);
        }
    }
    if (q == 0) {
        #pragma unroll
        for (int i = 0; i < 8; ++i) {
            atomicAdd(&g_sumc[b * C_ + cg * 8 + i], sv[i]);
            atomicAdd(&g_num [b * C_ + cg * 8 + i], sve[i]);
        }
    }
    if (w == 0) {
        #pragma unroll
        for (int off = 16; off > 0; off >>= 1) {
            run_e += __shfl_down_sync(0xffffffffu, run_e, off);
            run_m += __shfl_down_sync(0xffffffffu, run_m, off);
        }
        if (lane == 0) { atomicAdd(&g_D[b], run_e); atomicAdd(&g_summ[b], run_m); }
    }
    __threadfence();
    __syncthreads();
    if (t == 0) {
        unsigned old = atomicAdd(&g_cnt[b], 1u);
        s_last = (old == NBLK - 1);
    }
    __syncthreads();
    if (!s_last) return;

    // ================= finalize (last CTA of this batch) =================
    float* ctx   = sm;            // 256  (aliases AL/AM — loop fully done)
    float* bcv   = sm + 256;      // 256
    float* tvs   = sm + 512;      // 128
    float* tg    = sm + 640;      // 128
    float* sout  = sm + 768;      // 256
    float* red_s = sm + 1024;     // 4
    float* red_q = sm + 1028;     // 4
    float* red_a = sm + 1032;     // 8
    float* hid   = sm + 1040;     // 16
    float* o8    = sm + 1056;     // 8
    float* kar   = sm + 1064;     // 4
    float* fvv   = sm + 1072;     // 8
    float* shm   = sm + 1080;     // 1

    const int wp = w;

    const float Dv    = __ldcg(&g_D[b]);
    const float summv = __ldcg(&g_summ[b]);
    const float numv  = __ldcg(&g_num [b * C_ + t]);
    const float sumcv = __ldcg(&g_sumc[b * C_ + t]);

    ctx[t] = numv  * (1.f / Dv);
    bcv[t] = sumcv * (1.f / (float)HW_);
    {
        float s = sumcv * (1.f / (float)HW_);
        #pragma unroll
        for (int off = 16; off > 0; off >>= 1) s += __shfl_down_sync(0xffffffffu, s, off);
        if (lane == 0) red_a[wp] = s;
    }
    __syncthreads();   // RACE FIX: all threads have loaded g_* before any re-zero

    // re-zero scratch for next graph replay
    g_num [b * C_ + t] = 0.f;
    g_sumc[b * C_ + t] = 0.f;
    if (t == 0) { g_D[b] = 0.f; g_summ[b] = 0.f; g_cnt[b] = 0u; shm[0] = summv * (1.f / (float)HW_); }
    __syncthreads();

    const float aval = (red_a[0] + red_a[1] + red_a[2] + red_a[3] +
                        red_a[4] + red_a[5] + red_a[6] + red_a[7]) * (1.f / (float)C_);
    const float mv = shm[0];

    // conv1 (128x256): warp wp -> planes wp*16..+15
    {
        const float4* ctx4 = reinterpret_cast<const float4*>(ctx);
        const float4 c0 = ctx4[lane];
        const float4 c1 = ctx4[lane + 32];
        #pragma unroll 4
        for (int i = 0; i < 16; ++i) {
            int p = wp * 16 + i;
            const float4* w4 = reinterpret_cast<const float4*>(w_cm1 + p * C_);
            float4 a0 = w4[lane];
            float4 a1 = w4[lane + 32];
            float pr = a0.x * c0.x + a0.y * c0.y + a0.z * c0.z + a0.w * c0.w
                     + a1.x * c1.x + a1.y * c1.y + a1.z * c1.z + a1.w * c1.w;
            #pragma unroll
            for (int off = 16; off > 0; off >>= 1)
                pr += __shfl_down_sync(0xffffffffu, pr, off);
            if (lane == 0) tvs[p] = pr + b_cm1[p];
        }
    }
    __syncthreads();

    // LayerNorm(128) + exact GELU
    {
        float tvv = (t < PLANES) ? tvs[t] : 0.f;
        float s1 = tvv, s2 = tvv * tvv;
        #pragma unroll
        for (int off = 16; off > 0; off >>= 1) {
            s1 += __shfl_down_sync(0xffffffffu, s1, off);
            s2 += __shfl_down_sync(0xffffffffu, s2, off);
        }
        if (t < PLANES && lane == 0) { red_s[wp] = s1; red_q[wp] = s2; }
        __syncthreads();
        if (t < PLANES) {
            float S  = red_s[0] + red_s[1] + red_s[2] + red_s[3];
            float SQ = red_q[0] + red_q[1] + red_q[2] + red_q[3];
            float mu  = S * (1.f / PLANES);
            float var = SQ * (1.f / PLANES) - mu * mu;
            float tn = (tvv - mu) * rsqrtf(var + EPS_) * ln_w[t] + ln_b[t];
            tg[t] = 0.5f * tn * (1.f + erff(tn * 0.70710678118654752f));
        }
    }
    __syncthreads();

    // conv2 (256x128): warp wp -> channels wp*32..+31
    {
        const float4* tg4 = reinterpret_cast<const float4*>(tg);
        const float4 g0 = tg4[lane];
        #pragma unroll 4
        for (int i = 0; i < 32; ++i) {
            int ch = wp * 32 + i;
            const float4* w4 = reinterpret_cast<const float4*>(w_cm2 + ch * PLANES);
            float4 a0 = w4[lane];
            float pr = a0.x * g0.x + a0.y * g0.y + a0.z * g0.z + a0.w * g0.w;
            #pragma unroll
            for (int off = 16; off > 0; off >>= 1)
                pr += __shfl_down_sync(0xffffffffu, pr, off);
            if (lane == 0)
                sout[ch] = bcv[ch] + pr + b_cm2[ch] + ((ch & 1) ? mv : aval);
        }
    }
    __syncthreads();

    // net1 (16x256): warp wp -> hidden wp*2, wp*2+1
    {
        const float4* so4 = reinterpret_cast<const float4*>(sout);
        const float4 s0 = so4[lane];
        const float4 s1v = so4[lane + 32];
        #pragma unroll
        for (int jj = 0; jj < 2; ++jj) {
            int hh = wp * 2 + jj;
            const float4* w4 = reinterpret_cast<const float4*>(w_net1 + hh * C_);
            float4 a0 = w4[lane];
            float4 a1 = w4[lane + 32];
            float pr = a0.x * s0.x + a0.y * s0.y + a0.z * s0.z + a0.w * s0.w
                     + a1.x * s1v.x + a1.y * s1v.y + a1.z * s1v.z + a1.w * s1v.w;
            #pragma unroll
            for (int off = 16; off > 0; off >>= 1)
                pr += __shfl_down_sync(0xffffffffu, pr, off);
            if (lane == 0) hid[hh] = fmaxf(pr, 0.f);
        }
    }
    __syncthreads();

    if (t < K_) {
        float o = 0.f;
        #pragma unroll
        for (int q2 = 0; q2 < HIDDEN; ++q2) o = fmaf(hid[q2], w_net2[t * HIDDEN + q2], o);
        o8[t] = o;
    }
    __syncthreads();
    if (t < ATT_CH) {
        float ka = 0.f;
        #pragma unroll
        for (int k = 0; k < K_; ++k) ka = fmaf(o8[k], w_fc[t * K_ + k], ka);
        ka = (ka - bn_mean[t]) * rsqrtf(bn_var[t] + EPS_) * bn_w[t] + bn_b[t];
        kar[t] = fmaxf(ka, 0.f);
    }
    __syncthreads();
    if (t < K_) {
        float kk = 0.f;
        #pragma unroll
        for (int q2 = 0; q2 < ATT_CH; ++q2) kk = fmaf(kar[q2], w_kfc[t * ATT_CH + q2], kk);
        float ker = 1.f / (1.f + __expf(-kk));
        fvv[t] = o8[t] * ker * (1.f / 30.f);
    }
    __syncthreads();
    if (t == 0) {
        float mx = -1e30f;
        #pragma unroll
        for (int k = 0; k < K_; ++k) mx = fmaxf(mx, fvv[k]);
        float e[K_], s = 0.f;
        #pragma unroll
        for (int k = 0; k < K_; ++k) { e[k] = __expf(fvv[k] - mx); s += e[k]; }
        float inv = 1.f / s;
        #pragma unroll
        for (int k = 0; k < K_; ++k) out[b * K_ + k] = e[k] * inv;
    }
}

// ---------------- launch ----------------
extern "C" void kernel_launch(void* const* d_in, const int* in_sizes, int n_in,
                              void* d_out, int out_size) {
    const float* x      = (const float*)d_in[0];
    const float* w_mask = (const float*)d_in[1];
    const float* b_mask = (const float*)d_in[2];
    const float* w_cm1  = (const float*)d_in[3];
    const float* b_cm1  = (const float*)d_in[4];
    const float* ln_w   = (const float*)d_in[5];
    const float* ln_b   = (const float*)d_in[6];
    const float* w_cm2  = (const float*)d_in[7];
    const float* b_cm2  = (const float*)d_in[8];
    const float* w_net1 = (const float*)d_in[9];
    const float* w_net2 = (const float*)d_in[10];
    const float* w_fc   = (const float*)d_in[11];
    const float* bn_w   = (const float*)d_in[12];
    const float* bn_b   = (const float*)d_in[13];
    const float* bn_mean= (const float*)d_in[14];
    const float* bn_var = (const float*)d_in[15];
    const float* w_kfc  = (const float*)d_in[16];
    float* out = (float*)d_out;

    fused<<<B_ * NBLK, 256>>>(x, w_mask, b_mask,
                          w_cm1, b_cm1, ln_w, ln_b, w_cm2, b_cm2,
                          w_net1, w_net2, w_fc, bn_w, bn_b, bn_mean, bn_var,
                          w_kfc, out);
}